// round 1
// baseline (speedup 1.0000x reference)
#include <cuda_runtime.h>

// ---------------------------------------------------------------------------
// MMD^2 (RBF, gamma=1) over source/target 8192x16 fp32.
//
// n^2 * MMD^2 = sum_{a,b in [2n]^2} s_a s_b exp(-max(||p_a-p_b||^2, 0))
// with p = [X;Y], s = [+1...,-1...]. Symmetric -> tile upper triangle only.
// exp(-sq) = exp2(min(2*log2e*dot - (L|a|^2 + L|b|^2), 0)), L = log2e.
// ---------------------------------------------------------------------------

#define NSRC   8192
#define D      16
#define NP     16384          // 2 * NSRC
#define TILE   128
#define TB     (NP / TILE)    // 128 tile rows
#define LOG2E  1.4426950408889634f
#define TWOL   2.8853900817779268f

__device__ float  g_lsq[NP];        // LOG2E * ||p||^2 per point
__device__ double g_part[TB * TB];  // per-block signed/weighted partial sums

// ---- packed fp32x2 FMA (Blackwell fma pipe, 2x scalar FFMA throughput) ----
__device__ __forceinline__ void ffma2(float2& c, const float2 a, const float2 b) {
    asm("fma.rn.f32x2 %0, %1, %2, %0;"
        : "+l"(reinterpret_cast<unsigned long long&>(c))
        : "l"(reinterpret_cast<const unsigned long long&>(a)),
          "l"(reinterpret_cast<const unsigned long long&>(b)));
}

__device__ __forceinline__ float ex2(float x) {
    float r;
    asm("ex2.approx.f32 %0, %1;" : "=f"(r) : "f"(x));
    return r;
}

// ---------------------------------------------------------------------------
// Kernel 1: per-point scaled squared norms
// ---------------------------------------------------------------------------
__global__ void __launch_bounds__(256) norm_kernel(const float* __restrict__ src,
                                                   const float* __restrict__ tgt) {
    int p = blockIdx.x * 256 + threadIdx.x;
    if (p >= NP) return;
    const float* b = (p < NSRC) ? (src + (size_t)p * D) : (tgt + (size_t)(p - NSRC) * D);
    float s = 0.f;
#pragma unroll
    for (int d = 0; d < D; d += 4) {
        float4 v = *(const float4*)(b + d);
        s = fmaf(v.x, v.x, s);
        s = fmaf(v.y, v.y, s);
        s = fmaf(v.z, v.z, s);
        s = fmaf(v.w, v.w, s);
    }
    g_lsq[p] = LOG2E * s;
}

// ---------------------------------------------------------------------------
// Kernel 2: pairwise tile kernel. Block (tj, ti) computes 128x128 pair tile.
// SMEM layout: dimension-major [d][point] so j-side loads are contiguous
// float2 and i-side loads are warp-broadcast scalars.
// ---------------------------------------------------------------------------
__global__ void __launch_bounds__(256, 2) pair_kernel(const float* __restrict__ src,
                                                      const float* __restrict__ tgt) {
    const int ti  = blockIdx.y;
    const int tj  = blockIdx.x;
    const int tid = threadIdx.x;

    if (ti > tj) {                       // lower triangle: nothing to do
        if (tid == 0) g_part[ti * TB + tj] = 0.0;
        return;
    }

    __shared__ float sAt[D * TILE];      // [d][i]
    __shared__ float sBt[D * TILE];      // [d][j]
    __shared__ float sLA[TILE];
    __shared__ float sLB[TILE];

    // ---- load + transpose tiles (once per block; cost negligible) ----
    {
        const float* bA = (ti < TB / 2) ? (src + (size_t)ti * TILE * D)
                                        : (tgt + (size_t)(ti - TB / 2) * TILE * D);
        const float* bB = (tj < TB / 2) ? (src + (size_t)tj * TILE * D)
                                        : (tgt + (size_t)(tj - TB / 2) * TILE * D);
        int row = tid >> 1;              // 0..127 (point within tile)
        int c   = (tid & 1) * 8;         // 0 or 8 (dim offset)
        float4 a0 = *(const float4*)(bA + row * D + c);
        float4 a1 = *(const float4*)(bA + row * D + c + 4);
        float4 b0 = *(const float4*)(bB + row * D + c);
        float4 b1 = *(const float4*)(bB + row * D + c + 4);
        const float av[8] = {a0.x, a0.y, a0.z, a0.w, a1.x, a1.y, a1.z, a1.w};
        const float bv[8] = {b0.x, b0.y, b0.z, b0.w, b1.x, b1.y, b1.z, b1.w};
#pragma unroll
        for (int k = 0; k < 8; k++) {
            sAt[(c + k) * TILE + row] = av[k];
            sBt[(c + k) * TILE + row] = bv[k];
        }
        if (tid < TILE) sLA[tid] = g_lsq[ti * TILE + tid];
        else            sLB[tid - TILE] = g_lsq[tj * TILE + (tid - TILE)];
    }
    __syncthreads();

    const int tx = tid & 15;             // j-group
    const int ty = tid >> 4;             // i-group

    // register tile: i = ty + 16*ki (ki 0..7), j pairs (32m + 2tx, 32m + 2tx + 1)
    float2 acc[8][4];
#pragma unroll
    for (int ki = 0; ki < 8; ki++)
#pragma unroll
        for (int m = 0; m < 4; m++) acc[ki][m] = make_float2(0.f, 0.f);

#pragma unroll
    for (int d = 0; d < D; d++) {
        float2 bb[4];
#pragma unroll
        for (int m = 0; m < 4; m++)
            bb[m] = *(const float2*)(sBt + d * TILE + 32 * m + 2 * tx);
#pragma unroll
        for (int ki = 0; ki < 8; ki++) {
            float a = sAt[d * TILE + ty + 16 * ki];
            float2 aa = make_float2(a, a);
#pragma unroll
            for (int m = 0; m < 4; m++) ffma2(acc[ki][m], aa, bb[m]);
        }
    }

    // ---- epilogue: arg = min(2L*dot - (L|a|^2 + L|b|^2), 0); sum exp2(arg) ----
    float nla[8];
#pragma unroll
    for (int ki = 0; ki < 8; ki++) nla[ki] = -sLA[ty + 16 * ki];

    float tsum = 0.f;
#pragma unroll
    for (int m = 0; m < 4; m++) {
        float lb0 = sLB[32 * m + 2 * tx];
        float lb1 = sLB[32 * m + 2 * tx + 1];
#pragma unroll
        for (int ki = 0; ki < 8; ki++) {
            float arg0 = fminf(fmaf(acc[ki][m].x, TWOL, nla[ki] - lb0), 0.f);
            float arg1 = fminf(fmaf(acc[ki][m].y, TWOL, nla[ki] - lb1), 0.f);
            tsum += ex2(arg0);
            tsum += ex2(arg1);
        }
    }

    // ---- deterministic block reduction ----
#pragma unroll
    for (int off = 16; off; off >>= 1)
        tsum += __shfl_xor_sync(0xffffffffu, tsum, off);

    __shared__ float wsum[8];
    if ((tid & 31) == 0) wsum[tid >> 5] = tsum;
    __syncthreads();
    if (tid == 0) {
        double t = 0.0;
#pragma unroll
        for (int w = 0; w < 8; w++) t += (double)wsum[w];
        double wgt = (ti == tj) ? 1.0 : 2.0;
        double sgn = ((ti < TB / 2) == (tj < TB / 2)) ? 1.0 : -1.0;
        g_part[ti * TB + tj] = t * wgt * sgn;
    }
}

// ---------------------------------------------------------------------------
// Kernel 3: fixed-order double reduction of block partials -> scalar
// ---------------------------------------------------------------------------
__global__ void __launch_bounds__(256) finish_kernel(float* out) {
    __shared__ double s[256];
    int tid = threadIdx.x;
    double t = 0.0;
    for (int i = tid; i < TB * TB; i += 256) t += g_part[i];
    s[tid] = t;
    __syncthreads();
#pragma unroll
    for (int off = 128; off; off >>= 1) {
        if (tid < off) s[tid] += s[tid + off];
        __syncthreads();
    }
    if (tid == 0) out[0] = (float)(s[0] / 67108864.0);   // / n^2, n = 8192
}

// ---------------------------------------------------------------------------
extern "C" void kernel_launch(void* const* d_in, const int* in_sizes, int n_in,
                              void* d_out, int out_size) {
    const float* src = (const float*)d_in[0];
    const float* tgt = (const float*)d_in[1];

    norm_kernel<<<(NP + 255) / 256, 256>>>(src, tgt);
    dim3 grid(TB, TB);
    pair_kernel<<<grid, 256>>>(src, tgt);
    finish_kernel<<<1, 256>>>((float*)d_out);
}

// round 2
// speedup vs baseline: 1.0671x; 1.0671x over previous
#include <cuda_runtime.h>
#include <math.h>

// ---------------------------------------------------------------------------
// MMD^2 (RBF, gamma=1) over source/target 8192x16 fp32.
// n^2*MMD^2 = sum_{a,b} s_a s_b exp2(2L*dot(a,b) - L|a|^2 - L|b|^2), L=log2e.
// Symmetric -> upper-triangle tiles only (weight 2 off-diag).
// Trick: A-tile pre-scaled by 2L in SMEM, accumulators initialized to
// -L|a|^2 - L|b|^2  ==> mainloop output IS the exp2 argument. Epilogue is
// just MUFU.EX2 + packed accumulate.
// ---------------------------------------------------------------------------

#define NSRC   8192
#define D      16
#define NP     16384
#define TILE   128
#define TB     (NP / TILE)                 // 128
#define NBLK   (TB * (TB + 1) / 2)         // 8256 upper-triangle tiles
#define LOG2E  1.4426950408889634f
#define TWOL   2.8853900817779268f

__device__ double g_part[NBLK];

// ---- packed fp32x2 ops (Blackwell fma pipe, 2x scalar throughput) ----
__device__ __forceinline__ void ffma2(float2& c, const float2 a, const float2 b) {
    asm("fma.rn.f32x2 %0, %1, %2, %0;"
        : "+l"(reinterpret_cast<unsigned long long&>(c))
        : "l"(reinterpret_cast<const unsigned long long&>(a)),
          "l"(reinterpret_cast<const unsigned long long&>(b)));
}
__device__ __forceinline__ float2 fadd2(float2 a, float2 b) {
    float2 r;
    asm("add.rn.f32x2 %0, %1, %2;"
        : "=l"(reinterpret_cast<unsigned long long&>(r))
        : "l"(reinterpret_cast<const unsigned long long&>(a)),
          "l"(reinterpret_cast<const unsigned long long&>(b)));
    return r;
}
__device__ __forceinline__ float ex2(float x) {
    float r;
    asm("ex2.approx.f32 %0, %1;" : "=f"(r) : "f"(x));
    return r;
}

// start index of upper-triangle row t: f(t) = t*TB - t*(t-1)/2
__device__ __forceinline__ int tri_row_start(int t) {
    return t * TB - ((t * (t - 1)) >> 1);
}

// ---------------------------------------------------------------------------
// Pairwise tile kernel: linear bid -> (ti <= tj) 128x128 tile.
// ---------------------------------------------------------------------------
__global__ void __launch_bounds__(256, 2) pair_kernel(const float* __restrict__ src,
                                                      const float* __restrict__ tgt) {
    const int bid = blockIdx.x;
    const int tid = threadIdx.x;

    // bid -> (ti, tj), ti <= tj
    int ti = (int)((2.0 * TB + 1.0 - sqrt((2.0 * TB + 1.0) * (2.0 * TB + 1.0)
                                          - 8.0 * (double)bid)) * 0.5);
    while (tri_row_start(ti + 1) <= bid) ti++;
    while (tri_row_start(ti) > bid) ti--;
    const int tj = ti + (bid - tri_row_start(ti));

    __shared__ float sAt[D * TILE];    // [d][i], values pre-scaled by 2L
    __shared__ float sBt[D * TILE];    // [d][j]
    __shared__ float sLA[TILE];        // -L*|a_i|^2
    __shared__ float sLB[TILE];        // -L*|b_j|^2

    // ---- load + transpose tiles; fused norm computation ----
    {
        const float* bA = (ti < TB / 2) ? (src + (size_t)ti * TILE * D)
                                        : (tgt + (size_t)(ti - TB / 2) * TILE * D);
        const float* bB = (tj < TB / 2) ? (src + (size_t)tj * TILE * D)
                                        : (tgt + (size_t)(tj - TB / 2) * TILE * D);
        int row = tid >> 1;            // point within tile
        int c   = (tid & 1) * 8;       // dim offset: 0 or 8
        float4 a0 = *(const float4*)(bA + row * D + c);
        float4 a1 = *(const float4*)(bA + row * D + c + 4);
        float4 b0 = *(const float4*)(bB + row * D + c);
        float4 b1 = *(const float4*)(bB + row * D + c + 4);
        const float av[8] = {a0.x, a0.y, a0.z, a0.w, a1.x, a1.y, a1.z, a1.w};
        const float bv[8] = {b0.x, b0.y, b0.z, b0.w, b1.x, b1.y, b1.z, b1.w};

        float pa = 0.f, pb = 0.f;
#pragma unroll
        for (int k = 0; k < 8; k++) {
            pa = fmaf(av[k], av[k], pa);
            pb = fmaf(bv[k], bv[k], pb);
            sAt[(c + k) * TILE + row] = av[k] * TWOL;
            sBt[(c + k) * TILE + row] = bv[k];
        }
        pa += __shfl_xor_sync(0xffffffffu, pa, 1);
        pb += __shfl_xor_sync(0xffffffffu, pb, 1);
        if ((tid & 1) == 0) {
            sLA[row] = -LOG2E * pa;
            sLB[row] = -LOG2E * pb;
        }
    }
    __syncthreads();

    const int tx = tid & 15;           // j-group
    const int ty = tid >> 4;           // i-group

    // ---- init accumulators with the norm terms ----
    float2 acc[8][4];
    {
        float nla[8];
#pragma unroll
        for (int ki = 0; ki < 8; ki++) nla[ki] = sLA[ty + 16 * ki];
#pragma unroll
        for (int m = 0; m < 4; m++) {
            float2 lb = *(const float2*)(sLB + 32 * m + 2 * tx);
#pragma unroll
            for (int ki = 0; ki < 8; ki++)
                acc[ki][m] = fadd2(make_float2(nla[ki], nla[ki]), lb);
        }
    }

    // ---- mainloop: acc += (2L*a_d) * b_d  ->  acc ends as exp2 argument ----
#pragma unroll
    for (int d = 0; d < D; d++) {
        float2 bb[4];
#pragma unroll
        for (int m = 0; m < 4; m++)
            bb[m] = *(const float2*)(sBt + d * TILE + 32 * m + 2 * tx);
#pragma unroll
        for (int ki = 0; ki < 8; ki++) {
            float a = sAt[d * TILE + ty + 16 * ki];
            float2 aa = make_float2(a, a);
#pragma unroll
            for (int m = 0; m < 4; m++) ffma2(acc[ki][m], aa, bb[m]);
        }
    }

    // ---- epilogue: sum exp2(acc), 4 independent packed chains ----
    float2 vs[4];
#pragma unroll
    for (int m = 0; m < 4; m++) vs[m] = make_float2(0.f, 0.f);
#pragma unroll
    for (int m = 0; m < 4; m++)
#pragma unroll
        for (int ki = 0; ki < 8; ki++) {
            float2 e = make_float2(ex2(acc[ki][m].x), ex2(acc[ki][m].y));
            vs[m] = fadd2(vs[m], e);
        }
    float2 vt = fadd2(fadd2(vs[0], vs[1]), fadd2(vs[2], vs[3]));
    float tsum = vt.x + vt.y;

    // ---- deterministic block reduction ----
#pragma unroll
    for (int off = 16; off; off >>= 1)
        tsum += __shfl_xor_sync(0xffffffffu, tsum, off);

    __shared__ float wsum[8];
    if ((tid & 31) == 0) wsum[tid >> 5] = tsum;
    __syncthreads();
    if (tid == 0) {
        double t = 0.0;
#pragma unroll
        for (int w = 0; w < 8; w++) t += (double)wsum[w];
        double wgt = (ti == tj) ? 1.0 : 2.0;
        double sgn = ((ti < TB / 2) == (tj < TB / 2)) ? 1.0 : -1.0;
        g_part[bid] = t * wgt * sgn;
    }
}

// ---------------------------------------------------------------------------
// Final fixed-order double reduction -> scalar
// ---------------------------------------------------------------------------
__global__ void __launch_bounds__(256) finish_kernel(float* out) {
    __shared__ double s[256];
    int tid = threadIdx.x;
    double t = 0.0;
    for (int i = tid; i < NBLK; i += 256) t += g_part[i];
    s[tid] = t;
    __syncthreads();
#pragma unroll
    for (int off = 128; off; off >>= 1) {
        if (tid < off) s[tid] += s[tid + off];
        __syncthreads();
    }
    if (tid == 0) out[0] = (float)(s[0] / 67108864.0);   // / n^2, n = 8192
}

// ---------------------------------------------------------------------------
extern "C" void kernel_launch(void* const* d_in, const int* in_sizes, int n_in,
                              void* d_out, int out_size) {
    const float* src = (const float*)d_in[0];
    const float* tgt = (const float*)d_in[1];

    pair_kernel<<<NBLK, 256>>>(src, tgt);
    finish_kernel<<<1, 256>>>((float*)d_out);
}

// round 3
// speedup vs baseline: 1.0845x; 1.0163x over previous
#include <cuda_runtime.h>
#include <math.h>

// ---------------------------------------------------------------------------
// MMD^2 (RBF, gamma=1) over source/target 8192x16 fp32.
// n^2*MMD^2 = sum_{a,b} s_a s_b exp2(2L*dot(a,b) - L|a|^2 - L|b|^2), L=log2e.
// Symmetric -> upper-triangle tiles only (weight 2 off-diag).
// A-tile pre-scaled by 2L in SMEM; accumulators initialized to
// -L|a|^2 - L|b|^2 so the mainloop output IS the exp2 argument.
// ---------------------------------------------------------------------------

#define NSRC   8192
#define D      16
#define NP     16384
#define TILE   128
#define TB     (NP / TILE)                 // 128
#define NBLK   (TB * (TB + 1) / 2)         // 8256 upper-triangle tiles
#define LOG2E  1.4426950408889634f
#define TWOL   2.8853900817779268f

__device__ double g_part[NBLK];

// ---- packed fp32x2 ops (Blackwell fma pipe, 2x scalar throughput) ----
__device__ __forceinline__ void ffma2(float2& c, const float2 a, const float2 b) {
    asm("fma.rn.f32x2 %0, %1, %2, %0;"
        : "+l"(reinterpret_cast<unsigned long long&>(c))
        : "l"(reinterpret_cast<const unsigned long long&>(a)),
          "l"(reinterpret_cast<const unsigned long long&>(b)));
}
__device__ __forceinline__ float2 fadd2(float2 a, float2 b) {
    float2 r;
    asm("add.rn.f32x2 %0, %1, %2;"
        : "=l"(reinterpret_cast<unsigned long long&>(r))
        : "l"(reinterpret_cast<const unsigned long long&>(a)),
          "l"(reinterpret_cast<const unsigned long long&>(b)));
    return r;
}
__device__ __forceinline__ float ex2(float x) {
    float r;
    asm("ex2.approx.f32 %0, %1;" : "=f"(r) : "f"(x));
    return r;
}

__device__ __forceinline__ int tri_row_start(int t) {
    return t * TB - ((t * (t - 1)) >> 1);
}

// ---------------------------------------------------------------------------
// Pairwise tile kernel: linear bid -> (ti <= tj) 128x128 tile.
// Thread tile: 8 consecutive i x 8 consecutive j (LDS.128-friendly).
// ---------------------------------------------------------------------------
__global__ void __launch_bounds__(256, 2) pair_kernel(const float* __restrict__ src,
                                                      const float* __restrict__ tgt) {
    const int bid = blockIdx.x;
    const int tid = threadIdx.x;

    // bid -> (ti, tj), ti <= tj
    int ti = (int)((2.0 * TB + 1.0 - sqrt((2.0 * TB + 1.0) * (2.0 * TB + 1.0)
                                          - 8.0 * (double)bid)) * 0.5);
    while (tri_row_start(ti + 1) <= bid) ti++;
    while (tri_row_start(ti) > bid) ti--;
    const int tj = ti + (bid - tri_row_start(ti));

    __shared__ float sAt[D * TILE];    // [d][i], pre-scaled by 2L
    __shared__ float sBt[D * TILE];    // [d][j]
    __shared__ float sLA[TILE];        // -L*|a_i|^2
    __shared__ float sLB[TILE];        // -L*|b_j|^2

    // ---- load + transpose tiles; fused norm computation ----
    {
        const float* bA = (ti < TB / 2) ? (src + (size_t)ti * TILE * D)
                                        : (tgt + (size_t)(ti - TB / 2) * TILE * D);
        const float* bB = (tj < TB / 2) ? (src + (size_t)tj * TILE * D)
                                        : (tgt + (size_t)(tj - TB / 2) * TILE * D);
        int row = tid >> 1;            // point within tile
        int c   = (tid & 1) * 8;       // dim offset: 0 or 8
        float4 a0 = *(const float4*)(bA + row * D + c);
        float4 a1 = *(const float4*)(bA + row * D + c + 4);
        float4 b0 = *(const float4*)(bB + row * D + c);
        float4 b1 = *(const float4*)(bB + row * D + c + 4);
        const float av[8] = {a0.x, a0.y, a0.z, a0.w, a1.x, a1.y, a1.z, a1.w};
        const float bv[8] = {b0.x, b0.y, b0.z, b0.w, b1.x, b1.y, b1.z, b1.w};

        float pa = 0.f, pb = 0.f;
#pragma unroll
        for (int k = 0; k < 8; k++) {
            pa = fmaf(av[k], av[k], pa);
            pb = fmaf(bv[k], bv[k], pb);
            sAt[(c + k) * TILE + row] = av[k] * TWOL;
            sBt[(c + k) * TILE + row] = bv[k];
        }
        pa += __shfl_xor_sync(0xffffffffu, pa, 1);
        pb += __shfl_xor_sync(0xffffffffu, pb, 1);
        if ((tid & 1) == 0) {
            sLA[row] = -LOG2E * pa;
            sLB[row] = -LOG2E * pb;
        }
    }
    __syncthreads();

    const int jg = (tid & 15) * 8;     // 8 consecutive j
    const int ig = (tid >> 4) * 8;     // 8 consecutive i

    // ---- init accumulators with the norm terms ----
    float2 acc[8][4];                  // acc[ii][m] = (ig+ii, jg+2m .. +1)
    {
        float4 la0 = *(const float4*)(sLA + ig);
        float4 la1 = *(const float4*)(sLA + ig + 4);
        const float nla[8] = {la0.x, la0.y, la0.z, la0.w,
                              la1.x, la1.y, la1.z, la1.w};
        float4 lb0 = *(const float4*)(sLB + jg);
        float4 lb1 = *(const float4*)(sLB + jg + 4);
        const float2 lb[4] = {make_float2(lb0.x, lb0.y), make_float2(lb0.z, lb0.w),
                              make_float2(lb1.x, lb1.y), make_float2(lb1.z, lb1.w)};
#pragma unroll
        for (int ii = 0; ii < 8; ii++)
#pragma unroll
            for (int m = 0; m < 4; m++)
                acc[ii][m] = fadd2(make_float2(nla[ii], nla[ii]), lb[m]);
    }

    // ---- mainloop: acc += (2L*a_d) * b_d  ->  acc ends as exp2 argument ----
#pragma unroll
    for (int d = 0; d < D; d++) {
        const float* bd = sBt + d * TILE;
        const float* ad = sAt + d * TILE;
        float4 b0 = *(const float4*)(bd + jg);
        float4 b1 = *(const float4*)(bd + jg + 4);
        float4 a0 = *(const float4*)(ad + ig);
        float4 a1 = *(const float4*)(ad + ig + 4);
        const float2 bb[4] = {make_float2(b0.x, b0.y), make_float2(b0.z, b0.w),
                              make_float2(b1.x, b1.y), make_float2(b1.z, b1.w)};
        const float av[8] = {a0.x, a0.y, a0.z, a0.w, a1.x, a1.y, a1.z, a1.w};
#pragma unroll
        for (int ii = 0; ii < 8; ii++) {
            const float2 aa = make_float2(av[ii], av[ii]);
#pragma unroll
            for (int m = 0; m < 4; m++) ffma2(acc[ii][m], aa, bb[m]);
        }
    }

    // ---- epilogue: sum exp2(acc), 4 independent packed chains ----
    float2 vs[4];
#pragma unroll
    for (int m = 0; m < 4; m++) vs[m] = make_float2(0.f, 0.f);
#pragma unroll
    for (int m = 0; m < 4; m++)
#pragma unroll
        for (int ii = 0; ii < 8; ii++) {
            float2 e = make_float2(ex2(acc[ii][m].x), ex2(acc[ii][m].y));
            vs[m] = fadd2(vs[m], e);
        }
    float2 vt = fadd2(fadd2(vs[0], vs[1]), fadd2(vs[2], vs[3]));
    float tsum = vt.x + vt.y;

    // ---- deterministic block reduction ----
#pragma unroll
    for (int off = 16; off; off >>= 1)
        tsum += __shfl_xor_sync(0xffffffffu, tsum, off);

    __shared__ float wsum[8];
    if ((tid & 31) == 0) wsum[tid >> 5] = tsum;
    __syncthreads();
    if (tid == 0) {
        double t = 0.0;
#pragma unroll
        for (int w = 0; w < 8; w++) t += (double)wsum[w];
        double wgt = (ti == tj) ? 1.0 : 2.0;
        double sgn = ((ti < TB / 2) == (tj < TB / 2)) ? 1.0 : -1.0;
        g_part[bid] = t * wgt * sgn;
    }
}

// ---------------------------------------------------------------------------
// Final fixed-order double reduction -> scalar (512 threads, vectorized, MLP)
// ---------------------------------------------------------------------------
__global__ void __launch_bounds__(512) finish_kernel(float* out) {
    __shared__ double s[512];
    const int tid = threadIdx.x;
    const double2* p2 = (const double2*)g_part;       // NBLK = 8256 even
    double t0 = 0.0, t1 = 0.0;
#pragma unroll 4
    for (int i = tid; i < NBLK / 2; i += 512) {
        double2 v = p2[i];
        t0 += v.x;
        t1 += v.y;
    }
    s[tid] = t0 + t1;
    __syncthreads();
#pragma unroll
    for (int off = 256; off; off >>= 1) {
        if (tid < off) s[tid] += s[tid + off];
        __syncthreads();
    }
    if (tid == 0) out[0] = (float)(s[0] / 67108864.0);   // / n^2, n = 8192
}

// ---------------------------------------------------------------------------
extern "C" void kernel_launch(void* const* d_in, const int* in_sizes, int n_in,
                              void* d_out, int out_size) {
    const float* src = (const float*)d_in[0];
    const float* tgt = (const float*)d_in[1];

    pair_kernel<<<NBLK, 256>>>(src, tgt);
    finish_kernel<<<1, 512>>>((float*)d_out);
}

// round 6
// speedup vs baseline: 1.2732x; 1.1739x over previous
#include <cuda_runtime.h>
#include <cuda_bf16.h>
#include <math.h>
#include <stdint.h>

// ---------------------------------------------------------------------------
// MMD^2 (RBF, gamma=1), 8192x16 fp32, via mma.sync.m16n8k16 bf16 (sm_100 base).
//
// Coords scaled by sqrt(2*log2e), split x = hi + mid (bf16).
// A row: [hi(16) mid(16) hi(16) mid(16) | nh nm nl 1 1 1 | 0...]   (88 cols)
// B row: [hi(16) hi(16) mid(16) mid(16) | 1 1 1 nh nm nl | 0...]
// => GEMM output D = dot_s(a,b) - 0.5|a|_s^2 - 0.5|b|_s^2 = -log2e*||a-b||^2.
// Per-pair kernel value = ex2(D); we need only the SUM over the tile, so the
// mma fragment->element mapping is irrelevant. Upper-triangle tiles only.
// ---------------------------------------------------------------------------

#define NSRC   8192
#define D      16
#define NP     16384
#define TILE   128
#define TB     (NP / TILE)                 // 128
#define NBLK   (TB * (TB + 1) / 2)         // 8256
#define SQ2L   1.6986436004918308f         // sqrt(2*log2(e))
#define KPAD   88                          // padded row length (bf16)
#define ROWB   (KPAD * 2)                  // 176 bytes per row
#define NKC    5                           // K chunks of 16 (cols 0..79)
#define ATILEB (TILE * ROWB)               // 22528 bytes per tile side

// per point: u0,u1 = hi(16 bf16), u2,u3 = mid, u4 = normA unit, u5 = normB unit
__device__ uint4  g_S[NP * 6];
__device__ double g_part[NBLK];

// ---------------- helpers ----------------
__device__ __forceinline__ float ex2(float x) {
    float r; asm("ex2.approx.f32 %0, %1;" : "=f"(r) : "f"(x)); return r;
}
__device__ __forceinline__ uint32_t smem_u32(const void* p) {
    uint32_t a;
    asm("{ .reg .u64 t; cvta.to.shared.u64 t, %1; cvt.u32.u64 %0, t; }"
        : "=r"(a) : "l"(p));
    return a;
}
__device__ __forceinline__ void ldsm4(uint32_t* r, uint32_t addr) {
    asm volatile("ldmatrix.sync.aligned.m8n8.x4.shared.b16 {%0,%1,%2,%3}, [%4];"
                 : "=r"(r[0]), "=r"(r[1]), "=r"(r[2]), "=r"(r[3]) : "r"(addr));
}
__device__ __forceinline__ void mma16816(float* c, const uint32_t* a,
                                         uint32_t b0, uint32_t b1) {
    asm volatile("mma.sync.aligned.m16n8k16.row.col.f32.bf16.bf16.f32 "
                 "{%0,%1,%2,%3}, {%4,%5,%6,%7}, {%8,%9}, {%0,%1,%2,%3};"
                 : "+f"(c[0]), "+f"(c[1]), "+f"(c[2]), "+f"(c[3])
                 : "r"(a[0]), "r"(a[1]), "r"(a[2]), "r"(a[3]), "r"(b0), "r"(b1));
}
__device__ __forceinline__ int tri_row_start(int t) {
    return t * TB - ((t * (t - 1)) >> 1);
}

// ---------------------------------------------------------------------------
// Kernel 1: scale, hi/mid split, 3-way-split norm units.
// ---------------------------------------------------------------------------
__global__ void __launch_bounds__(256) split_kernel(const float* __restrict__ src,
                                                    const float* __restrict__ tgt) {
    int p = blockIdx.x * 256 + threadIdx.x;
    if (p >= NP) return;
    const float* x = (p < NSRC) ? (src + (size_t)p * D) : (tgt + (size_t)(p - NSRC) * D);

    uint4 u[6];
    __nv_bfloat16* hi  = (__nv_bfloat16*)&u[0];
    __nv_bfloat16* mid = (__nv_bfloat16*)&u[2];
    __nv_bfloat16* nA  = (__nv_bfloat16*)&u[4];
    __nv_bfloat16* nB  = (__nv_bfloat16*)&u[5];

    float ns = 0.f;
#pragma unroll
    for (int d = 0; d < D; d++) {
        float v = x[d] * SQ2L;
        ns = fmaf(v, v, ns);
        __nv_bfloat16 h = __float2bfloat16(v);
        float r1 = v - __bfloat162float(h);
        hi[d]  = h;
        mid[d] = __float2bfloat16(r1);
    }
    float na = -0.5f * ns;
    __nv_bfloat16 nh = __float2bfloat16(na);
    float nr1 = na - __bfloat162float(nh);
    __nv_bfloat16 nm = __float2bfloat16(nr1);
    __nv_bfloat16 nl = __float2bfloat16(nr1 - __bfloat162float(nm));
    const __nv_bfloat16 one  = __float2bfloat16(1.0f);
    const __nv_bfloat16 zero = __float2bfloat16(0.0f);

    nA[0] = nh;  nA[1] = nm;  nA[2] = nl;  nA[3] = one; nA[4] = one; nA[5] = one;
    nA[6] = zero; nA[7] = zero;
    nB[0] = one; nB[1] = one; nB[2] = one; nB[3] = nh;  nB[4] = nm;  nB[5] = nl;
    nB[6] = zero; nB[7] = zero;

    uint4* out = g_S + (size_t)p * 6;
#pragma unroll
    for (int i = 0; i < 6; i++) out[i] = u[i];
}

// ---------------------------------------------------------------------------
// Kernel 2: pairwise 128x128 tiles via bf16 mma.sync.
// Warp w: rows (w&3)*32 + {0,16}, cols (w>>2)*64 (8 n8-tiles).
// ---------------------------------------------------------------------------
__global__ void __launch_bounds__(256, 2) pair_kernel() {
    extern __shared__ __align__(16) char dsm[];
    __shared__ float wsum[8];

    const int bid  = blockIdx.x;
    const int tid  = threadIdx.x;
    const int lane = tid & 31;
    const int w    = tid >> 5;

    int ti = (int)((2.0 * TB + 1.0 - sqrt((2.0 * TB + 1.0) * (2.0 * TB + 1.0)
                                          - 8.0 * (double)bid)) * 0.5);
    while (tri_row_start(ti + 1) <= bid) ti++;
    while (tri_row_start(ti) > bid) ti--;
    const int tj = ti + (bid - tri_row_start(ti));

    // ---- build A/B tiles in SMEM (row stride 176B; conflict-free ldmatrix) ----
    {
        const int  row = tid & 127;
        const bool isA = tid < 128;
        const uint4* srow = g_S + (size_t)(((isA ? ti : tj) * TILE) + row) * 6;
        char* rbase = dsm + (isA ? 0 : ATILEB) + row * ROWB;

        uint4 u[6];
#pragma unroll
        for (int i = 0; i < 6; i++) u[i] = srow[i];

        // c16-unit source per 16B column chunk (11 chunks = 176B):
        // A: [hi hi mid mid hi hi mid mid nA 0 0]
        // B: [hi hi hi hi mid mid mid mid nB 0 0]
        const int mapA[11] = {0,1, 2,3, 0,1, 2,3, 4, -1, -1};
        const int mapB[11] = {0,1, 0,1, 2,3, 2,3, 5, -1, -1};
#pragma unroll
        for (int c = 0; c < 11; c++) {
            int s = isA ? mapA[c] : mapB[c];
            uint4 v = (s >= 0) ? u[s] : make_uint4(0u, 0u, 0u, 0u);
            *(uint4*)(rbase + c * 16) = v;
        }
    }
    __syncthreads();

    const uint32_t sA = smem_u32(dsm);
    const uint32_t sB = sA + ATILEB;
    const int mbase = (w & 3) * 32;
    const int nbase = (w >> 2) * 64;

    // ldmatrix lane address bases (col-chunk offset added per K step)
    const uint32_t aRow  = (uint32_t)(mbase + (lane & 7) + ((lane >> 3) & 1) * 8);
    const uint32_t aAddr0 = sA + aRow * ROWB + ((lane >> 4) & 1) * 16;
    const uint32_t aAddr1 = aAddr0 + 16 * ROWB;
    const uint32_t bRowQ = (uint32_t)((lane & 7) + ((lane >> 4) & 1) * 8);
    const uint32_t bColH = ((lane >> 3) & 1) * 16;
    uint32_t bAddr[4];
#pragma unroll
    for (int q = 0; q < 4; q++)
        bAddr[q] = sB + (uint32_t)(nbase + 16 * q + bRowQ) * ROWB + bColH;

    float acc[2][8][4];
#pragma unroll
    for (int mt = 0; mt < 2; mt++)
#pragma unroll
        for (int nt = 0; nt < 8; nt++)
#pragma unroll
            for (int e = 0; e < 4; e++) acc[mt][nt][e] = 0.f;

#pragma unroll
    for (int kc = 0; kc < NKC; kc++) {
        const uint32_t ko = kc * 32;          // 16 bf16 = 32 bytes per chunk
        uint32_t a0[4], a1[4], b[4][4];
        ldsm4(a0, aAddr0 + ko);
        ldsm4(a1, aAddr1 + ko);
#pragma unroll
        for (int q = 0; q < 4; q++) ldsm4(b[q], bAddr[q] + ko);
#pragma unroll
        for (int nt = 0; nt < 8; nt++) {
            const uint32_t b0 = b[nt >> 1][(nt & 1) * 2];
            const uint32_t b1 = b[nt >> 1][(nt & 1) * 2 + 1];
            mma16816(acc[0][nt], a0, b0, b1);
            mma16816(acc[1][nt], a1, b0, b1);
        }
    }

    // ---- epilogue: sum ex2 over all accumulator elements (mapping-free) ----
    float s0 = 0.f, s1 = 0.f, s2 = 0.f, s3 = 0.f;
#pragma unroll
    for (int mt = 0; mt < 2; mt++)
#pragma unroll
        for (int nt = 0; nt < 8; nt++) {
            s0 += ex2(acc[mt][nt][0]);
            s1 += ex2(acc[mt][nt][1]);
            s2 += ex2(acc[mt][nt][2]);
            s3 += ex2(acc[mt][nt][3]);
        }
    float tsum = (s0 + s1) + (s2 + s3);
#pragma unroll
    for (int off = 16; off; off >>= 1)
        tsum += __shfl_xor_sync(0xffffffffu, tsum, off);
    if (lane == 0) wsum[w] = tsum;
    __syncthreads();

    if (tid == 0) {
        double t = 0.0;
#pragma unroll
        for (int x = 0; x < 8; x++) t += (double)wsum[x];
        double wgt = (ti == tj) ? 1.0 : 2.0;
        double sgn = ((ti < TB / 2) == (tj < TB / 2)) ? 1.0 : -1.0;
        g_part[bid] = t * wgt * sgn;
    }
}

// ---------------------------------------------------------------------------
// Kernel 3: fixed-order double reduction -> scalar
// ---------------------------------------------------------------------------
__global__ void __launch_bounds__(512) finish_kernel(float* out) {
    __shared__ double s[512];
    const int tid = threadIdx.x;
    const double2* p2 = (const double2*)g_part;       // NBLK even
    double t0 = 0.0, t1 = 0.0;
#pragma unroll 4
    for (int i = tid; i < NBLK / 2; i += 512) {
        double2 v = p2[i];
        t0 += v.x;
        t1 += v.y;
    }
    s[tid] = t0 + t1;
    __syncthreads();
#pragma unroll
    for (int off = 256; off; off >>= 1) {
        if (tid < off) s[tid] += s[tid + off];
        __syncthreads();
    }
    if (tid == 0) out[0] = (float)(s[0] / 67108864.0);   // / n^2, n = 8192
}

// ---------------------------------------------------------------------------
extern "C" void kernel_launch(void* const* d_in, const int* in_sizes, int n_in,
                              void* d_out, int out_size) {
    const float* src = (const float*)d_in[0];
    const float* tgt = (const float*)d_in[1];

    const int smem_bytes = 2 * ATILEB;     // 45056 B
    cudaFuncSetAttribute(pair_kernel, cudaFuncAttributeMaxDynamicSharedMemorySize,
                         smem_bytes);

    split_kernel<<<(NP + 255) / 256, 256>>>(src, tgt);
    pair_kernel<<<NBLK, 256, smem_bytes>>>();
    finish_kernel<<<1, 512>>>((float*)d_out);
}